// round 16
// baseline (speedup 1.0000x reference)
#include <cuda_runtime.h>
#include <cuda_bf16.h>
#include <math.h>
#include <stdint.h>

// Problem dims
#define T_DIM 4096
#define B_DIM 8
#define C_DIM 1024
#define F_DIM 128
#define NPROJ 6
#define N6 (NPROJ * F_DIM)          // 768
#define M_DIM (T_DIM * B_DIM)       // 32768
#define G_GRP 32                    // row groups per batch for scan
#define R_ROWS (F_DIM / G_GRP)      // 4 rows per warp

#define INV_SQRT_F 0.08838834764831845f  // 1/sqrt(128)

// Scan SMEM pipeline
#define CHUNK 8                     // steps per chunk (33KB: co-resident w/ K1)
#define SLOT_F 528                  // floats per step slot
#define BUF_F (CHUNK * SLOT_F)
#define SCAN_SMEM (2 * BUF_F * 4)   // 33792 bytes

#define NTILES_M (M_DIM / 128)      // 256 bm tiles (16 t-steps each)
#define NTILES_N (N6 / 128)         // 6

// ---------------------------------------------------------------------------
// Scratch
// ---------------------------------------------------------------------------
__device__ float d_b6[N6];
__device__ float d_P[(size_t)M_DIM * N6];                             // 96 MB
__device__ float d_opart[(size_t)M_DIM * G_GRP * F_DIM];              // 512 MB
__device__ float d_stfb[(size_t)B_DIM * F_DIM * F_DIM];
__device__ int   d_flags[NTILES_M];                                   // K1->scan
__device__ __nv_bfloat16 d_xh[(size_t)M_DIM * C_DIM];
__device__ __nv_bfloat16 d_xl[(size_t)M_DIM * C_DIM];
__device__ __nv_bfloat16 d_W6h[(size_t)N6 * C_DIM];
__device__ __nv_bfloat16 d_W6l[(size_t)N6 * C_DIM];
__device__ __nv_bfloat16 d_Owh[(size_t)C_DIM * F_DIM];
__device__ __nv_bfloat16 d_Owl[(size_t)C_DIM * F_DIM];
__device__ __nv_bfloat16 d_oh[(size_t)M_DIM * F_DIM];
__device__ __nv_bfloat16 d_ol[(size_t)M_DIM * F_DIM];

// ---------------------------------------------------------------------------
// helpers
// ---------------------------------------------------------------------------
__device__ __forceinline__ void split1(float v, __nv_bfloat16& h, __nv_bfloat16& l) {
    h = __float2bfloat16_rn(v);
    l = __float2bfloat16_rn(v - __bfloat162float(h));
}

__device__ __forceinline__ void cp16(uint32_t dst, const void* src) {
    asm volatile("cp.async.ca.shared.global [%0], [%1], 16;"
                 :: "r"(dst), "l"(src));
}

// ---------------------------------------------------------------------------
// K0: pack biases + split weights + split x + zero flags
// ---------------------------------------------------------------------------
__global__ void pack_split_kernel(
    const float* __restrict__ xin,
    const float* __restrict__ Aw, const float* __restrict__ Bw,
    const float* __restrict__ Cw, const float* __restrict__ Dw,
    const float* __restrict__ Iw, const float* __restrict__ Sw,
    const float* __restrict__ Ab, const float* __restrict__ Bb,
    const float* __restrict__ Cb, const float* __restrict__ Db,
    const float* __restrict__ Ib, const float* __restrict__ Sb,
    const float* __restrict__ Ow)
{
    size_t i4 = (size_t)blockIdx.x * blockDim.x + threadIdx.x;
    const size_t total4 = (size_t)M_DIM * C_DIM / 4;
    if (i4 < total4) {
        float4 v = ((const float4*)xin)[i4];
        __nv_bfloat16 h0, l0, h1, l1, h2, l2, h3, l3;
        split1(v.x, h0, l0); split1(v.y, h1, l1);
        split1(v.z, h2, l2); split1(v.w, h3, l3);
        uint2 ph, pl;
        ph.x = (uint32_t)__bfloat16_as_ushort(h0) | ((uint32_t)__bfloat16_as_ushort(h1) << 16);
        ph.y = (uint32_t)__bfloat16_as_ushort(h2) | ((uint32_t)__bfloat16_as_ushort(h3) << 16);
        pl.x = (uint32_t)__bfloat16_as_ushort(l0) | ((uint32_t)__bfloat16_as_ushort(l1) << 16);
        pl.y = (uint32_t)__bfloat16_as_ushort(l2) | ((uint32_t)__bfloat16_as_ushort(l3) << 16);
        ((uint2*)d_xh)[i4] = ph;
        ((uint2*)d_xl)[i4] = pl;
    }
    const size_t per = (size_t)F_DIM * C_DIM;  // 131072
    if (i4 < per) {
        size_t i = i4;
        split1(Aw[i], d_W6h[0 * per + i], d_W6l[0 * per + i]);
        split1(Bw[i], d_W6h[1 * per + i], d_W6l[1 * per + i]);
        split1(Cw[i], d_W6h[2 * per + i], d_W6l[2 * per + i]);
        split1(Dw[i], d_W6h[3 * per + i], d_W6l[3 * per + i]);
        split1(Iw[i], d_W6h[4 * per + i], d_W6l[4 * per + i]);
        split1(Sw[i], d_W6h[5 * per + i], d_W6l[5 * per + i]);
        split1(Ow[i], d_Owh[i], d_Owl[i]);
    }
    if (i4 < F_DIM) {
        size_t i = i4;
        d_b6[0 * F_DIM + i] = Ab[i];
        d_b6[1 * F_DIM + i] = Bb[i];
        d_b6[2 * F_DIM + i] = Cb[i];
        d_b6[3 * F_DIM + i] = Db[i];
        d_b6[4 * F_DIM + i] = Ib[i];
        d_b6[5 * F_DIM + i] = Sb[i];
    }
    if (i4 < NTILES_M) d_flags[i4] = 0;
}

// ---------------------------------------------------------------------------
// K1/K4: 3xBF16 GEMM, cp.async pipeline + ldmatrix + mma.m16n8k16 (NT).
// K1 epilogue: slot-b scale, slot-i sigmoid. If flags != nullptr, each CTA
// publishes completion of its bm tile (release pattern) for the scan.
// ---------------------------------------------------------------------------
#define ASTRIDE 40
#define TILE_E (128 * ASTRIDE)
#define TILE_B (TILE_E * 2)
#define STAGE_B (4 * TILE_B)
#define GEMM_SMEM (2 * STAGE_B)

__device__ __forceinline__ void ldm_x4(uint32_t (&r)[4], const __nv_bfloat16* p) {
    uint32_t addr = (uint32_t)__cvta_generic_to_shared(p);
    asm volatile("ldmatrix.sync.aligned.m8n8.x4.shared.b16 {%0,%1,%2,%3}, [%4];"
                 : "=r"(r[0]), "=r"(r[1]), "=r"(r[2]), "=r"(r[3]) : "r"(addr));
}

__device__ __forceinline__ void mma_bf16(float* d, const uint32_t* a,
                                         uint32_t b0, uint32_t b1) {
    asm volatile(
        "mma.sync.aligned.m16n8k16.row.col.f32.bf16.bf16.f32 "
        "{%0,%1,%2,%3}, {%4,%5,%6,%7}, {%8,%9}, {%0,%1,%2,%3};"
        : "+f"(d[0]), "+f"(d[1]), "+f"(d[2]), "+f"(d[3])
        : "r"(a[0]), "r"(a[1]), "r"(a[2]), "r"(a[3]), "r"(b0), "r"(b1));
}

__device__ __forceinline__ float epi_op(float v, int mode) {
    if (mode == 1) return v * INV_SQRT_F;
    if (mode == 2) return 1.0f / (1.0f + __expf(-v));
    return v;
}

__global__ void __launch_bounds__(256, 2)
bf16_gemm_async(const __nv_bfloat16* __restrict__ Ah,
                const __nv_bfloat16* __restrict__ Al,
                const __nv_bfloat16* __restrict__ Bh,
                const __nv_bfloat16* __restrict__ Bl,
                const float* __restrict__ bias, float* __restrict__ C,
                int M, int N, int K, int* flags)
{
    extern __shared__ __align__(16) __nv_bfloat16 smd[];

    const int tid = threadIdx.x;
    const int wid = tid >> 5;
    const int lane = tid & 31;
    const int grp = lane >> 2;
    const int tig = lane & 3;

    const int bm = blockIdx.y * 128;
    const int bn = blockIdx.x * 128;
    const int warp_m = (wid >> 1) * 32;
    const int warp_n = (wid & 1) * 64;

    float acc[2][8][4];
#pragma unroll
    for (int mt = 0; mt < 2; mt++)
#pragma unroll
        for (int nt = 0; nt < 8; nt++)
#pragma unroll
            for (int q = 0; q < 4; q++) acc[mt][nt][q] = 0.0f;

    const int lrow = tid >> 1;
    const int cb = (tid & 1) * 2;

    const __nv_bfloat16* gsrc[4];
    gsrc[0] = Ah + (size_t)(bm + lrow) * K;
    gsrc[1] = Al + (size_t)(bm + lrow) * K;
    gsrc[2] = Bh + (size_t)(bn + lrow) * K;
    gsrc[3] = Bl + (size_t)(bn + lrow) * K;

    const uint32_t smem_base = (uint32_t)__cvta_generic_to_shared(smd);
    const uint32_t dst0 = smem_base + (uint32_t)(lrow * ASTRIDE * 2 + cb * 16);

    const int a_e0 = (warp_m + (lane & 15)) * ASTRIDE + ((lane >> 4) & 1) * 8;
    const int b_e0 = (warp_n + (lane & 7) + ((lane >> 4) & 1) * 8) * ASTRIDE
                   + ((lane >> 3) & 1) * 8;

#define ISSUE_STAGE(stg, kk) do {                                          \
    uint32_t _d = dst0 + (uint32_t)(stg) * STAGE_B;                        \
    _Pragma("unroll")                                                      \
    for (int _m = 0; _m < 4; _m++) {                                       \
        cp16(_d + 0,  gsrc[_m] + (kk) + (cb + 0) * 8);                     \
        cp16(_d + 16, gsrc[_m] + (kk) + (cb + 1) * 8);                     \
        _d += TILE_B;                                                      \
    }                                                                      \
    asm volatile("cp.async.commit_group;");                                \
} while (0)

    const int niter = K >> 5;
    ISSUE_STAGE(0, 0);

    for (int i = 0; i < niter; i++) {
        if (i + 1 < niter) {
            ISSUE_STAGE((i + 1) & 1, (i + 1) * 32);
            asm volatile("cp.async.wait_group 1;");
        } else {
            asm volatile("cp.async.wait_group 0;");
        }
        __syncthreads();

        const __nv_bfloat16* sAh = smd + (size_t)((i & 1) * 4 + 0) * TILE_E;
        const __nv_bfloat16* sAl = smd + (size_t)((i & 1) * 4 + 1) * TILE_E;
        const __nv_bfloat16* sBh = smd + (size_t)((i & 1) * 4 + 2) * TILE_E;
        const __nv_bfloat16* sBl = smd + (size_t)((i & 1) * 4 + 3) * TILE_E;

#pragma unroll
        for (int ks = 0; ks < 2; ks++) {
            uint32_t afh[2][4], afl[2][4];
#pragma unroll
            for (int mt = 0; mt < 2; mt++) {
                int e = a_e0 + mt * 16 * ASTRIDE + ks * 16;
                ldm_x4(afh[mt], sAh + e);
                ldm_x4(afl[mt], sAl + e);
            }
#pragma unroll
            for (int ntp = 0; ntp < 4; ntp++) {
                uint32_t bh[4], bl[4];
                int e = b_e0 + ntp * 16 * ASTRIDE + ks * 16;
                ldm_x4(bh, sBh + e);
                ldm_x4(bl, sBl + e);
#pragma unroll
                for (int mt = 0; mt < 2; mt++) {
                    mma_bf16(acc[mt][2 * ntp],     afh[mt], bh[0], bh[1]);
                    mma_bf16(acc[mt][2 * ntp],     afh[mt], bl[0], bl[1]);
                    mma_bf16(acc[mt][2 * ntp],     afl[mt], bh[0], bh[1]);
                    mma_bf16(acc[mt][2 * ntp + 1], afh[mt], bh[2], bh[3]);
                    mma_bf16(acc[mt][2 * ntp + 1], afh[mt], bl[2], bl[3]);
                    mma_bf16(acc[mt][2 * ntp + 1], afl[mt], bh[2], bh[3]);
                }
            }
        }
        __syncthreads();
    }
#undef ISSUE_STAGE

    int mode = 0;
    if (bias != nullptr && N == N6) {
        if (bn == 1 * F_DIM) mode = 1;        // slot b: scale by 1/sqrt(F)
        else if (bn == 4 * F_DIM) mode = 2;   // slot i: sigmoid
    }

#pragma unroll
    for (int mt = 0; mt < 2; mt++) {
        int r0 = bm + warp_m + mt * 16 + grp;
#pragma unroll
        for (int nt = 0; nt < 8; nt++) {
            int col = bn + warp_n + nt * 8 + 2 * tig;
            float b0 = 0.f, b1 = 0.f;
            if (bias != nullptr) { b0 = bias[col]; b1 = bias[col + 1]; }
            float2 v0 = make_float2(epi_op(acc[mt][nt][0] + b0, mode),
                                    epi_op(acc[mt][nt][1] + b1, mode));
            float2 v1 = make_float2(epi_op(acc[mt][nt][2] + b0, mode),
                                    epi_op(acc[mt][nt][3] + b1, mode));
            *(float2*)(C + (size_t)r0 * N + col) = v0;
            *(float2*)(C + (size_t)(r0 + 8) * N + col) = v1;
        }
    }

    // publish tile completion for the overlapped scan (release pattern)
    if (flags != nullptr) {
        __threadfence();
        __syncthreads();
        if (tid == 0) atomicAdd(&flags[blockIdx.y], 1);
    }
}

// ---------------------------------------------------------------------------
// K2: sequential scan, G=32, 4 rows per warp, CHUNK=8 SMEM ring.
// Waits on K1's per-bm-tile flags before issuing each chunk (overlap).
// Slot layout (floats): a[0..127], b'[128..255], d[256..383], g[384..511],
//                       c[512..515], s[516..519], pad -> SLOT_F
// ---------------------------------------------------------------------------
__global__ void __launch_bounds__(32)
scan_kernel(const float* __restrict__ P, const float* __restrict__ state_in,
            float* __restrict__ opart, float* __restrict__ state_out,
            const int* __restrict__ flags)
{
    extern __shared__ __align__(16) float sm[];

    const int g = blockIdx.x;
    const int b = blockIdx.y;
    const int l = threadIdx.x;
    const int rowbase = g * R_ROWS;

    const uint32_t smb = (uint32_t)__cvta_generic_to_shared(sm);

    // wait until the bm tile containing chunk cc is fully written (6 bn tiles)
#define WAIT_CHUNK(cc) do {                                                   \
    const volatile int* _f = (const volatile int*)&flags[(cc) >> 1];          \
    while (*_f < NTILES_N) __nanosleep(128);                                  \
    __threadfence();                                                          \
} while (0)

#define ISSUE_CHUNK(cc, bi) do {                                              \
    const int _t0 = (cc) * CHUNK;                                             \
    _Pragma("unroll 4")                                                       \
    for (int _s = 0; _s < CHUNK; _s++) {                                      \
        const float* _src = P + (size_t)((size_t)(_t0 + _s) * B_DIM + b) * N6;\
        uint32_t _dst = smb + (uint32_t)(((bi) * BUF_F + _s * SLOT_F) * 4);   \
        cp16(_dst + (uint32_t)(l * 16),          _src + 0 * F_DIM + l * 4);   \
        cp16(_dst + (uint32_t)(512 + l * 16),    _src + 1 * F_DIM + l * 4);   \
        cp16(_dst + (uint32_t)(1024 + l * 16),   _src + 3 * F_DIM + l * 4);   \
        cp16(_dst + (uint32_t)(1536 + l * 16),   _src + 4 * F_DIM + l * 4);   \
        if (l == 0) cp16(_dst + 2048, _src + 2 * F_DIM + rowbase);            \
        if (l == 1) cp16(_dst + 2064, _src + 5 * F_DIM + rowbase);            \
    }                                                                         \
    asm volatile("cp.async.commit_group;");                                   \
} while (0)

    // initial state
    float4 st[R_ROWS];
    {
        const float* sb = state_in + ((size_t)b * F_DIM + rowbase) * F_DIM + 4 * l;
#pragma unroll
        for (int r = 0; r < R_ROWS; r++)
            st[r] = *(const float4*)(sb + r * F_DIM);
    }

    WAIT_CHUNK(0);
    ISSUE_CHUNK(0, 0);
    WAIT_CHUNK(1);
    ISSUE_CHUNK(1, 1);

    const bool hi16 = (l & 16) != 0;
    const bool hi8 = (l & 8) != 0;

    const int NCHUNK = T_DIM / CHUNK;   // 512
#pragma unroll 1
    for (int cc = 0; cc < NCHUNK; cc++) {
        asm volatile("cp.async.wait_group 1;");
        __syncwarp();

        const int bi = cc & 1;
        const float* buf = sm + (size_t)bi * BUF_F;

#pragma unroll 4
        for (int s = 0; s < CHUNK; s++) {
            const int t = cc * CHUNK + s;
            const float* sp = buf + s * SLOT_F;

            float4 a  = *(const float4*)(sp + 4 * l);
            float4 bb = *(const float4*)(sp + 128 + 4 * l);   // pre-scaled
            float4 dd = *(const float4*)(sp + 256 + 4 * l);
            float4 gg = *(const float4*)(sp + 384 + 4 * l);   // pre-sigmoided

            // per-lane partial dots
            float p[R_ROWS];
#pragma unroll
            for (int r = 0; r < R_ROWS; r++) {
                float m01 = fmaf(st[r].y, a.y, st[r].x * a.x);
                float m23 = fmaf(st[r].w, a.w, st[r].z * a.z);
                p[r] = m01 + m23;
            }

            // 10-shfl 4-way allsum
            float sA = hi16 ? p[0] : p[2];
            float sB = hi16 ? p[1] : p[3];
            float rA = __shfl_xor_sync(0xffffffffu, sA, 16);
            float rB = __shfl_xor_sync(0xffffffffu, sB, 16);
            float q0 = (hi16 ? p[2] : p[0]) + rA;
            float q1 = (hi16 ? p[3] : p[1]) + rB;
            float sC = hi8 ? q0 : q1;
            float rC = __shfl_xor_sync(0xffffffffu, sC, 8);
            float w = (hi8 ? q1 : q0) + rC;
            w += __shfl_xor_sync(0xffffffffu, w, 4);
            w += __shfl_xor_sync(0xffffffffu, w, 2);
            w += __shfl_xor_sync(0xffffffffu, w, 1);
            float v[R_ROWS];
            v[0] = __shfl_sync(0xffffffffu, w, 0);
            v[1] = __shfl_sync(0xffffffffu, w, 8);
            v[2] = __shfl_sync(0xffffffffu, w, 16);
            v[3] = __shfl_sync(0xffffffffu, w, 24);

            float cc4[R_ROWS], ss4[R_ROWS];
#pragma unroll
            for (int r = 0; r < R_ROWS; r++) {
                cc4[r] = sp[512 + r];
                ss4[r] = sp[516 + r];
            }

            float4 po = make_float4(0.f, 0.f, 0.f, 0.f);
#pragma unroll
            for (int r = 0; r < R_ROWS; r++) {
                const float cr = cc4[r];
                st[r].x = fmaf(st[r].x, gg.x, fmaf(v[r], bb.x, cr * dd.x));
                st[r].y = fmaf(st[r].y, gg.y, fmaf(v[r], bb.y, cr * dd.y));
                st[r].z = fmaf(st[r].z, gg.z, fmaf(v[r], bb.z, cr * dd.z));
                st[r].w = fmaf(st[r].w, gg.w, fmaf(v[r], bb.w, cr * dd.w));
                const float sr = ss4[r];
                po.x = fmaf(sr, st[r].x, po.x);
                po.y = fmaf(sr, st[r].y, po.y);
                po.z = fmaf(sr, st[r].z, po.z);
                po.w = fmaf(sr, st[r].w, po.w);
            }
            float* ob = opart +
                ((size_t)((size_t)t * B_DIM + b) * G_GRP + g) * F_DIM + 4 * l;
            *(float4*)ob = po;
        }

        __syncwarp();
        if (cc + 2 < NCHUNK) {
            WAIT_CHUNK(cc + 2);
            ISSUE_CHUNK(cc + 2, bi);
        }
    }
#undef ISSUE_CHUNK
#undef WAIT_CHUNK

    float* so = state_out + ((size_t)b * F_DIM + rowbase) * F_DIM + 4 * l;
#pragma unroll
    for (int r = 0; r < R_ROWS; r++)
        *(float4*)(so + r * F_DIM) = st[r];
}

// ---------------------------------------------------------------------------
// K3: reduce partial outputs over G, emitting bf16 hi/lo for K4
// ---------------------------------------------------------------------------
__global__ void reduce_opart_kernel(const float* __restrict__ opart)
{
    const int F4 = F_DIM / 4;
    size_t idx = (size_t)blockIdx.x * blockDim.x + threadIdx.x;
    size_t total = (size_t)M_DIM * F4;
    if (idx >= total) return;
    size_t row = idx / F4;
    int f4 = (int)(idx % F4);
    const float4* src = (const float4*)opart + row * (size_t)(G_GRP * F4) + f4;
    float4 acc = make_float4(0.f, 0.f, 0.f, 0.f);
#pragma unroll
    for (int gg = 0; gg < G_GRP; gg++) {
        float4 xv = src[(size_t)gg * F4];
        acc.x += xv.x; acc.y += xv.y; acc.z += xv.z; acc.w += xv.w;
    }
    __nv_bfloat16 h0, l0, h1, l1, h2, l2, h3, l3;
    split1(acc.x, h0, l0); split1(acc.y, h1, l1);
    split1(acc.z, h2, l2); split1(acc.w, h3, l3);
    uint2 ph, pl;
    ph.x = (uint32_t)__bfloat16_as_ushort(h0) | ((uint32_t)__bfloat16_as_ushort(h1) << 16);
    ph.y = (uint32_t)__bfloat16_as_ushort(h2) | ((uint32_t)__bfloat16_as_ushort(h3) << 16);
    pl.x = (uint32_t)__bfloat16_as_ushort(l0) | ((uint32_t)__bfloat16_as_ushort(l1) << 16);
    pl.y = (uint32_t)__bfloat16_as_ushort(l2) | ((uint32_t)__bfloat16_as_ushort(l3) << 16);
    ((uint2*)d_oh)[idx] = ph;
    ((uint2*)d_ol)[idx] = pl;
}

// ---------------------------------------------------------------------------
// launch — forks the capture stream: K1 on main, scan (flag-gated) on s2.
// ---------------------------------------------------------------------------
extern "C" void kernel_launch(void* const* d_in, const int* in_sizes, int n_in,
                              void* d_out, int out_size)
{
    const float* x     = (const float*)d_in[0];
    const float* state = (const float*)d_in[1];
    const float* A_w = (const float*)d_in[2];
    const float* A_b = (const float*)d_in[3];
    const float* B_w = (const float*)d_in[4];
    const float* B_b = (const float*)d_in[5];
    const float* C_w = (const float*)d_in[6];
    const float* C_b = (const float*)d_in[7];
    const float* D_w = (const float*)d_in[8];
    const float* D_b = (const float*)d_in[9];
    const float* I_w = (const float*)d_in[10];
    const float* I_b = (const float*)d_in[11];
    const float* S_w = (const float*)d_in[12];
    const float* S_b = (const float*)d_in[13];
    const float* O_w = (const float*)d_in[14];

    float* out = (float*)d_out;

    float *b6, *P, *opart, *stfb;
    int* flags;
    __nv_bfloat16 *xh, *xl, *W6h, *W6l, *Owh, *Owl, *oh, *ol;
    cudaGetSymbolAddress((void**)&b6, d_b6);
    cudaGetSymbolAddress((void**)&P, d_P);
    cudaGetSymbolAddress((void**)&opart, d_opart);
    cudaGetSymbolAddress((void**)&stfb, d_stfb);
    cudaGetSymbolAddress((void**)&flags, d_flags);
    cudaGetSymbolAddress((void**)&xh, d_xh);
    cudaGetSymbolAddress((void**)&xl, d_xl);
    cudaGetSymbolAddress((void**)&W6h, d_W6h);
    cudaGetSymbolAddress((void**)&W6l, d_W6l);
    cudaGetSymbolAddress((void**)&Owh, d_Owh);
    cudaGetSymbolAddress((void**)&Owl, d_Owl);
    cudaGetSymbolAddress((void**)&oh, d_oh);
    cudaGetSymbolAddress((void**)&ol, d_ol);

    cudaFuncSetAttribute(bf16_gemm_async,
                         cudaFuncAttributeMaxDynamicSharedMemorySize, GEMM_SMEM);
    cudaFuncSetAttribute(scan_kernel,
                         cudaFuncAttributeMaxDynamicSharedMemorySize, SCAN_SMEM);

    const size_t y_elems = (size_t)M_DIM * C_DIM;
    const size_t st_elems = (size_t)B_DIM * F_DIM * F_DIM;
    float* y = out;
    float* state_out =
        ((size_t)out_size >= y_elems + st_elems) ? (out + y_elems) : stfb;

    // fork resources (host objects, created per call; no device allocation)
    cudaStream_t s2;
    cudaStreamCreateWithFlags(&s2, cudaStreamNonBlocking);
    cudaEvent_t ev1, ev2;
    cudaEventCreateWithFlags(&ev1, cudaEventDisableTiming);
    cudaEventCreateWithFlags(&ev2, cudaEventDisableTiming);

    // main: pack/split (also zeroes flags)
    {
        size_t total4 = (size_t)M_DIM * C_DIM / 4;
        pack_split_kernel<<<(unsigned)((total4 + 255) / 256), 256>>>(
            x, A_w, B_w, C_w, D_w, I_w, S_w,
            A_b, B_b, C_b, D_b, I_b, S_b, O_w);
    }
    cudaEventRecord(ev1, 0);

    // main: K1 (publishes per-tile flags)
    {
        dim3 grid(NTILES_N, NTILES_M);
        bf16_gemm_async<<<grid, 256, GEMM_SMEM>>>(xh, xl, W6h, W6l, b6, P,
                                                  M_DIM, N6, C_DIM, flags);
    }

    // s2: scan, overlapped with K1, gated by flags
    cudaStreamWaitEvent(s2, ev1, 0);
    {
        dim3 grid(G_GRP, B_DIM);
        scan_kernel<<<grid, 32, SCAN_SMEM, s2>>>(P, state, opart, state_out,
                                                 flags);
    }
    cudaEventRecord(ev2, s2);
    cudaStreamWaitEvent(0, ev2, 0);

    // main: reduce partials -> bf16 hi/lo o
    {
        size_t total = (size_t)M_DIM * (F_DIM / 4);
        reduce_opart_kernel<<<(unsigned)((total + 255) / 256), 256>>>(opart);
    }

    // main: K4  y = o @ O_w^T
    {
        dim3 grid(C_DIM / 128, M_DIM / 128);
        bf16_gemm_async<<<grid, 256, GEMM_SMEM>>>(oh, ol, Owh, Owl, nullptr, y,
                                                  M_DIM, C_DIM, F_DIM, nullptr);
    }
}

// round 17
// speedup vs baseline: 1.1659x; 1.1659x over previous
#include <cuda_runtime.h>
#include <cuda_bf16.h>
#include <math.h>
#include <stdint.h>

// Problem dims
#define T_DIM 4096
#define B_DIM 8
#define C_DIM 1024
#define F_DIM 128
#define NPROJ 6
#define N6 (NPROJ * F_DIM)          // 768
#define M_DIM (T_DIM * B_DIM)       // 32768
#define G_GRP 32                    // row groups per batch for scan
#define R_ROWS (F_DIM / G_GRP)      // 4 rows per warp

#define INV_SQRT_F 0.08838834764831845f  // 1/sqrt(128)

// Scan SMEM pipeline: 3 buffers of 8-step chunks
#define CHUNK 8
#define NBUF 3
#define SLOT_F 528                  // a[0..127] b'[128..255] d[256..383] g[384..511]
                                    // c[512..515] s[516..519] bg[520..521] pad
#define BUF_F (CHUNK * SLOT_F)
#define SCAN_SMEM (NBUF * BUF_F * 4)  // 50688 bytes

// ---------------------------------------------------------------------------
// Scratch
// ---------------------------------------------------------------------------
__device__ float d_b6[N6];
__device__ float d_P[(size_t)M_DIM * N6];                             // 96 MB
__device__ float d_opart[(size_t)M_DIM * G_GRP * F_DIM];              // 512 MB
__device__ float d_stfb[(size_t)B_DIM * F_DIM * F_DIM];
__device__ float2 d_bg[(size_t)T_DIM * B_DIM];                        // beta/gamma
__device__ __nv_bfloat16 d_xh[(size_t)M_DIM * C_DIM];
__device__ __nv_bfloat16 d_xl[(size_t)M_DIM * C_DIM];
__device__ __nv_bfloat16 d_W6h[(size_t)N6 * C_DIM];
__device__ __nv_bfloat16 d_W6l[(size_t)N6 * C_DIM];
__device__ __nv_bfloat16 d_Owh[(size_t)C_DIM * F_DIM];
__device__ __nv_bfloat16 d_Owl[(size_t)C_DIM * F_DIM];
__device__ __nv_bfloat16 d_oh[(size_t)M_DIM * F_DIM];
__device__ __nv_bfloat16 d_ol[(size_t)M_DIM * F_DIM];

// ---------------------------------------------------------------------------
// helpers
// ---------------------------------------------------------------------------
__device__ __forceinline__ void split1(float v, __nv_bfloat16& h, __nv_bfloat16& l) {
    h = __float2bfloat16_rn(v);
    l = __float2bfloat16_rn(v - __bfloat162float(h));
}

__device__ __forceinline__ void cp16(uint32_t dst, const void* src) {
    asm volatile("cp.async.ca.shared.global [%0], [%1], 16;"
                 :: "r"(dst), "l"(src));
}

__device__ __forceinline__ void cp8(uint32_t dst, const void* src) {
    asm volatile("cp.async.ca.shared.global [%0], [%1], 8;"
                 :: "r"(dst), "l"(src));
}

// ---------------------------------------------------------------------------
// K0: pack biases + split weights + split x
// ---------------------------------------------------------------------------
__global__ void pack_split_kernel(
    const float* __restrict__ xin,
    const float* __restrict__ Aw, const float* __restrict__ Bw,
    const float* __restrict__ Cw, const float* __restrict__ Dw,
    const float* __restrict__ Iw, const float* __restrict__ Sw,
    const float* __restrict__ Ab, const float* __restrict__ Bb,
    const float* __restrict__ Cb, const float* __restrict__ Db,
    const float* __restrict__ Ib, const float* __restrict__ Sb,
    const float* __restrict__ Ow)
{
    size_t i4 = (size_t)blockIdx.x * blockDim.x + threadIdx.x;
    const size_t total4 = (size_t)M_DIM * C_DIM / 4;
    if (i4 < total4) {
        float4 v = ((const float4*)xin)[i4];
        __nv_bfloat16 h0, l0, h1, l1, h2, l2, h3, l3;
        split1(v.x, h0, l0); split1(v.y, h1, l1);
        split1(v.z, h2, l2); split1(v.w, h3, l3);
        uint2 ph, pl;
        ph.x = (uint32_t)__bfloat16_as_ushort(h0) | ((uint32_t)__bfloat16_as_ushort(h1) << 16);
        ph.y = (uint32_t)__bfloat16_as_ushort(h2) | ((uint32_t)__bfloat16_as_ushort(h3) << 16);
        pl.x = (uint32_t)__bfloat16_as_ushort(l0) | ((uint32_t)__bfloat16_as_ushort(l1) << 16);
        pl.y = (uint32_t)__bfloat16_as_ushort(l2) | ((uint32_t)__bfloat16_as_ushort(l3) << 16);
        ((uint2*)d_xh)[i4] = ph;
        ((uint2*)d_xl)[i4] = pl;
    }
    const size_t per = (size_t)F_DIM * C_DIM;
    if (i4 < per) {
        size_t i = i4;
        split1(Aw[i], d_W6h[0 * per + i], d_W6l[0 * per + i]);
        split1(Bw[i], d_W6h[1 * per + i], d_W6l[1 * per + i]);
        split1(Cw[i], d_W6h[2 * per + i], d_W6l[2 * per + i]);
        split1(Dw[i], d_W6h[3 * per + i], d_W6l[3 * per + i]);
        split1(Iw[i], d_W6h[4 * per + i], d_W6l[4 * per + i]);
        split1(Sw[i], d_W6h[5 * per + i], d_W6l[5 * per + i]);
        split1(Ow[i], d_Owh[i], d_Owl[i]);
    }
    if (i4 < F_DIM) {
        size_t i = i4;
        d_b6[0 * F_DIM + i] = Ab[i];
        d_b6[1 * F_DIM + i] = Bb[i];
        d_b6[2 * F_DIM + i] = Cb[i];
        d_b6[3 * F_DIM + i] = Db[i];
        d_b6[4 * F_DIM + i] = Ib[i];
        d_b6[5 * F_DIM + i] = Sb[i];
    }
}

// ---------------------------------------------------------------------------
// K1/K4: 3xBF16 GEMM (cp.async + ldmatrix + mma). K1 epilogue: slot-b scale,
// slot-i sigmoid.
// ---------------------------------------------------------------------------
#define ASTRIDE 40
#define TILE_E (128 * ASTRIDE)
#define TILE_B (TILE_E * 2)
#define STAGE_B (4 * TILE_B)
#define GEMM_SMEM (2 * STAGE_B)

__device__ __forceinline__ void ldm_x4(uint32_t (&r)[4], const __nv_bfloat16* p) {
    uint32_t addr = (uint32_t)__cvta_generic_to_shared(p);
    asm volatile("ldmatrix.sync.aligned.m8n8.x4.shared.b16 {%0,%1,%2,%3}, [%4];"
                 : "=r"(r[0]), "=r"(r[1]), "=r"(r[2]), "=r"(r[3]) : "r"(addr));
}

__device__ __forceinline__ void mma_bf16(float* d, const uint32_t* a,
                                         uint32_t b0, uint32_t b1) {
    asm volatile(
        "mma.sync.aligned.m16n8k16.row.col.f32.bf16.bf16.f32 "
        "{%0,%1,%2,%3}, {%4,%5,%6,%7}, {%8,%9}, {%0,%1,%2,%3};"
        : "+f"(d[0]), "+f"(d[1]), "+f"(d[2]), "+f"(d[3])
        : "r"(a[0]), "r"(a[1]), "r"(a[2]), "r"(a[3]), "r"(b0), "r"(b1));
}

__device__ __forceinline__ float epi_op(float v, int mode) {
    if (mode == 1) return v * INV_SQRT_F;
    if (mode == 2) return 1.0f / (1.0f + __expf(-v));
    return v;
}

__global__ void __launch_bounds__(256, 2)
bf16_gemm_async(const __nv_bfloat16* __restrict__ Ah,
                const __nv_bfloat16* __restrict__ Al,
                const __nv_bfloat16* __restrict__ Bh,
                const __nv_bfloat16* __restrict__ Bl,
                const float* __restrict__ bias, float* __restrict__ C,
                int M, int N, int K)
{
    extern __shared__ __align__(16) __nv_bfloat16 smd[];

    const int tid = threadIdx.x;
    const int wid = tid >> 5;
    const int lane = tid & 31;
    const int grp = lane >> 2;
    const int tig = lane & 3;

    const int bm = blockIdx.y * 128;
    const int bn = blockIdx.x * 128;
    const int warp_m = (wid >> 1) * 32;
    const int warp_n = (wid & 1) * 64;

    float acc[2][8][4];
#pragma unroll
    for (int mt = 0; mt < 2; mt++)
#pragma unroll
        for (int nt = 0; nt < 8; nt++)
#pragma unroll
            for (int q = 0; q < 4; q++) acc[mt][nt][q] = 0.0f;

    const int lrow = tid >> 1;
    const int cb = (tid & 1) * 2;

    const __nv_bfloat16* gsrc[4];
    gsrc[0] = Ah + (size_t)(bm + lrow) * K;
    gsrc[1] = Al + (size_t)(bm + lrow) * K;
    gsrc[2] = Bh + (size_t)(bn + lrow) * K;
    gsrc[3] = Bl + (size_t)(bn + lrow) * K;

    const uint32_t smem_base = (uint32_t)__cvta_generic_to_shared(smd);
    const uint32_t dst0 = smem_base + (uint32_t)(lrow * ASTRIDE * 2 + cb * 16);

    const int a_e0 = (warp_m + (lane & 15)) * ASTRIDE + ((lane >> 4) & 1) * 8;
    const int b_e0 = (warp_n + (lane & 7) + ((lane >> 4) & 1) * 8) * ASTRIDE
                   + ((lane >> 3) & 1) * 8;

#define ISSUE_STAGE(stg, kk) do {                                          \
    uint32_t _d = dst0 + (uint32_t)(stg) * STAGE_B;                        \
    _Pragma("unroll")                                                      \
    for (int _m = 0; _m < 4; _m++) {                                       \
        cp16(_d + 0,  gsrc[_m] + (kk) + (cb + 0) * 8);                     \
        cp16(_d + 16, gsrc[_m] + (kk) + (cb + 1) * 8);                     \
        _d += TILE_B;                                                      \
    }                                                                      \
    asm volatile("cp.async.commit_group;");                                \
} while (0)

    const int niter = K >> 5;
    ISSUE_STAGE(0, 0);

    for (int i = 0; i < niter; i++) {
        if (i + 1 < niter) {
            ISSUE_STAGE((i + 1) & 1, (i + 1) * 32);
            asm volatile("cp.async.wait_group 1;");
        } else {
            asm volatile("cp.async.wait_group 0;");
        }
        __syncthreads();

        const __nv_bfloat16* sAh = smd + (size_t)((i & 1) * 4 + 0) * TILE_E;
        const __nv_bfloat16* sAl = smd + (size_t)((i & 1) * 4 + 1) * TILE_E;
        const __nv_bfloat16* sBh = smd + (size_t)((i & 1) * 4 + 2) * TILE_E;
        const __nv_bfloat16* sBl = smd + (size_t)((i & 1) * 4 + 3) * TILE_E;

#pragma unroll
        for (int ks = 0; ks < 2; ks++) {
            uint32_t afh[2][4], afl[2][4];
#pragma unroll
            for (int mt = 0; mt < 2; mt++) {
                int e = a_e0 + mt * 16 * ASTRIDE + ks * 16;
                ldm_x4(afh[mt], sAh + e);
                ldm_x4(afl[mt], sAl + e);
            }
#pragma unroll
            for (int ntp = 0; ntp < 4; ntp++) {
                uint32_t bh[4], bl[4];
                int e = b_e0 + ntp * 16 * ASTRIDE + ks * 16;
                ldm_x4(bh, sBh + e);
                ldm_x4(bl, sBl + e);
#pragma unroll
                for (int mt = 0; mt < 2; mt++) {
                    mma_bf16(acc[mt][2 * ntp],     afh[mt], bh[0], bh[1]);
                    mma_bf16(acc[mt][2 * ntp],     afh[mt], bl[0], bl[1]);
                    mma_bf16(acc[mt][2 * ntp],     afl[mt], bh[0], bh[1]);
                    mma_bf16(acc[mt][2 * ntp + 1], afh[mt], bh[2], bh[3]);
                    mma_bf16(acc[mt][2 * ntp + 1], afh[mt], bl[2], bl[3]);
                    mma_bf16(acc[mt][2 * ntp + 1], afl[mt], bh[2], bh[3]);
                }
            }
        }
        __syncthreads();
    }
#undef ISSUE_STAGE

    int mode = 0;
    if (bias != nullptr && N == N6) {
        if (bn == 1 * F_DIM) mode = 1;
        else if (bn == 4 * F_DIM) mode = 2;
    }

#pragma unroll
    for (int mt = 0; mt < 2; mt++) {
        int r0 = bm + warp_m + mt * 16 + grp;
#pragma unroll
        for (int nt = 0; nt < 8; nt++) {
            int col = bn + warp_n + nt * 8 + 2 * tig;
            float b0 = 0.f, b1 = 0.f;
            if (bias != nullptr) { b0 = bias[col]; b1 = bias[col + 1]; }
            float2 v0 = make_float2(epi_op(acc[mt][nt][0] + b0, mode),
                                    epi_op(acc[mt][nt][1] + b1, mode));
            float2 v1 = make_float2(epi_op(acc[mt][nt][2] + b0, mode),
                                    epi_op(acc[mt][nt][3] + b1, mode));
            *(float2*)(C + (size_t)r0 * N + col) = v0;
            *(float2*)(C + (size_t)(r0 + 8) * N + col) = v1;
        }
    }
}

// ---------------------------------------------------------------------------
// K1b: precompute beta[t] = b'_t . a_{t+1}, gamma[t] = d_t . a_{t+1}
// one warp per (t, b). t = T-1 -> zeros.
// ---------------------------------------------------------------------------
__global__ void __launch_bounds__(256)
bg_kernel(const float* __restrict__ P, float2* __restrict__ bgout)
{
    int idx = blockIdx.x * 8 + (threadIdx.x >> 5);   // global warp id
    int lane = threadIdx.x & 31;
    int t = idx / B_DIM;
    int b = idx % B_DIM;
    if (t >= T_DIM) return;
    float bb = 0.f, gg = 0.f;
    if (t < T_DIM - 1) {
        const float* p0 = P + ((size_t)t * B_DIM + b) * N6;
        const float* p1 = P + ((size_t)(t + 1) * B_DIM + b) * N6;
        float4 bv = *(const float4*)(p0 + 1 * F_DIM + 4 * lane);  // b' (scaled)
        float4 dv = *(const float4*)(p0 + 3 * F_DIM + 4 * lane);  // d
        float4 av = *(const float4*)(p1 + 0 * F_DIM + 4 * lane);  // a_{t+1}
        bb = fmaf(bv.w, av.w, fmaf(bv.z, av.z, fmaf(bv.y, av.y, bv.x * av.x)));
        gg = fmaf(dv.w, av.w, fmaf(dv.z, av.z, fmaf(dv.y, av.y, dv.x * av.x)));
#pragma unroll
        for (int o = 16; o >= 1; o >>= 1) {
            bb += __shfl_xor_sync(0xffffffffu, bb, o);
            gg += __shfl_xor_sync(0xffffffffu, gg, o);
        }
    }
    if (lane == 0) bgout[(size_t)t * B_DIM + b] = make_float2(bb, gg);
}

// ---------------------------------------------------------------------------
// K2: scan with lookahead-1 pipelined reduction.
// v_{t+1}[r] = sum_j S_{t-1}[r,j]*(g_t*a_{t+1})[j] + beta_t*v_t[r] + gamma_t*c_t[r]
// Each iteration launches the reduce for the NEXT v from the OLD state, so
// consecutive shfl chains pipeline with the update/output work.
// ---------------------------------------------------------------------------
__global__ void __launch_bounds__(32)
scan_kernel(const float* __restrict__ P, const float* __restrict__ state_in,
            const float2* __restrict__ bg, float* __restrict__ opart,
            float* __restrict__ state_out)
{
    extern __shared__ __align__(16) float sm[];

    const int g = blockIdx.x;
    const int b = blockIdx.y;
    const int l = threadIdx.x;
    const int rowbase = g * R_ROWS;

    const uint32_t smb = (uint32_t)__cvta_generic_to_shared(sm);

#define ISSUE_CHUNK(cc) do {                                                  \
    const int _t0 = (cc) * CHUNK;                                             \
    const int _bi = (cc) % NBUF;                                              \
    _Pragma("unroll 4")                                                       \
    for (int _s = 0; _s < CHUNK; _s++) {                                      \
        const float* _src = P + (size_t)((size_t)(_t0 + _s) * B_DIM + b) * N6;\
        uint32_t _dst = smb + (uint32_t)((_bi * BUF_F + _s * SLOT_F) * 4);    \
        cp16(_dst + (uint32_t)(l * 16),          _src + 0 * F_DIM + l * 4);   \
        cp16(_dst + (uint32_t)(512 + l * 16),    _src + 1 * F_DIM + l * 4);   \
        cp16(_dst + (uint32_t)(1024 + l * 16),   _src + 3 * F_DIM + l * 4);   \
        cp16(_dst + (uint32_t)(1536 + l * 16),   _src + 4 * F_DIM + l * 4);   \
        if (l == 0) cp16(_dst + 2048, _src + 2 * F_DIM + rowbase);            \
        if (l == 1) cp16(_dst + 2064, _src + 5 * F_DIM + rowbase);            \
        if (l == 2) cp8(_dst + 2080, bg + (size_t)(_t0 + _s) * B_DIM + b);    \
    }                                                                         \
    asm volatile("cp.async.commit_group;");                                   \
} while (0)

// 10-shfl 4-way allsum: p[0..3] -> out[0..3] broadcast
#define ALLSUM4(p, out) do {                                                  \
    float _sA = hi16 ? (p)[0] : (p)[2];                                       \
    float _sB = hi16 ? (p)[1] : (p)[3];                                       \
    float _rA = __shfl_xor_sync(0xffffffffu, _sA, 16);                        \
    float _rB = __shfl_xor_sync(0xffffffffu, _sB, 16);                        \
    float _q0 = (hi16 ? (p)[2] : (p)[0]) + _rA;                               \
    float _q1 = (hi16 ? (p)[3] : (p)[1]) + _rB;                               \
    float _sC = hi8 ? _q0 : _q1;                                              \
    float _rC = __shfl_xor_sync(0xffffffffu, _sC, 8);                         \
    float _w = (hi8 ? _q1 : _q0) + _rC;                                       \
    _w += __shfl_xor_sync(0xffffffffu, _w, 4);                                \
    _w += __shfl_xor_sync(0xffffffffu, _w, 2);                                \
    _w += __shfl_xor_sync(0xffffffffu, _w, 1);                                \
    (out)[0] = __shfl_sync(0xffffffffu, _w, 0);                               \
    (out)[1] = __shfl_sync(0xffffffffu, _w, 8);                               \
    (out)[2] = __shfl_sync(0xffffffffu, _w, 16);                              \
    (out)[3] = __shfl_sync(0xffffffffu, _w, 24);                              \
} while (0)

    const bool hi16 = (l & 16) != 0;
    const bool hi8 = (l & 8) != 0;

    // initial state
    float4 st[R_ROWS];
    {
        const float* sb = state_in + ((size_t)b * F_DIM + rowbase) * F_DIM + 4 * l;
#pragma unroll
        for (int r = 0; r < R_ROWS; r++)
            st[r] = *(const float4*)(sb + r * F_DIM);
    }

    ISSUE_CHUNK(0);
    ISSUE_CHUNK(1);
    ISSUE_CHUNK(2);
    asm volatile("cp.async.wait_group 1;");   // chunks 0,1 resident
    __syncwarp();

    // prologue: direct reduce R0 = S_init . a_0  (v_0 = R0 in iteration 0)
    float R[R_ROWS];
    {
        const float* sp0 = sm;
        float4 a0 = *(const float4*)(sp0 + 4 * l);
        float p[R_ROWS];
#pragma unroll
        for (int r = 0; r < R_ROWS; r++) {
            float m01 = fmaf(st[r].y, a0.y, st[r].x * a0.x);
            float m23 = fmaf(st[r].w, a0.w, st[r].z * a0.z);
            p[r] = m01 + m23;
        }
        ALLSUM4(p, R);
    }

    float vcur[R_ROWS] = {0.f, 0.f, 0.f, 0.f};
    float cprev[R_ROWS] = {0.f, 0.f, 0.f, 0.f};
    float bprev = 0.f, gprev = 0.f;

    const int NCHUNK = T_DIM / CHUNK;   // 512
#pragma unroll 1
    for (int cc = 0; cc < NCHUNK; cc++) {
        if (cc) {
            asm volatile("cp.async.wait_group 1;");  // chunks cc, cc+1 resident
            __syncwarp();
        }
        const float* buf  = sm + (size_t)(cc % NBUF) * BUF_F;
        const float* bufn = sm + (size_t)((cc + 1) % NBUF) * BUF_F;

#pragma unroll
        for (int s = 0; s < CHUNK; s++) {
            const int t = cc * CHUNK + s;
            const float* sp = buf + s * SLOT_F;
            const float* spn = (s < CHUNK - 1) ? (sp + SLOT_F) : bufn;

            float4 bb = *(const float4*)(sp + 128 + 4 * l);   // b' (scaled)
            float4 dd = *(const float4*)(sp + 256 + 4 * l);
            float4 gg = *(const float4*)(sp + 384 + 4 * l);   // sigmoided
            float4 an = *(const float4*)(spn + 4 * l);        // a_{t+1}
            float cs[R_ROWS], ss[R_ROWS];
#pragma unroll
            for (int r = 0; r < R_ROWS; r++) {
                cs[r] = sp[512 + r];
                ss[r] = sp[516 + r];
            }
            const float beta  = sp[520];
            const float gamma = sp[521];

            // (1') partials for R_{t+1} from OLD state: ga = g_t * a_{t+1}
            float4 ga;
            ga.x = gg.x * an.x; ga.y = gg.y * an.y;
            ga.z = gg.z * an.z; ga.w = gg.w * an.w;
            float p[R_ROWS];
#pragma unroll
            for (int r = 0; r < R_ROWS; r++) {
                float m01 = fmaf(st[r].y, ga.y, st[r].x * ga.x);
                float m23 = fmaf(st[r].w, ga.w, st[r].z * ga.z);
                p[r] = m01 + m23;
            }
            float Rn[R_ROWS];
            ALLSUM4(p, Rn);   // shfl chain; result consumed NEXT iteration

            // (2') finalize v_t from previous chain
            float vt[R_ROWS];
#pragma unroll
            for (int r = 0; r < R_ROWS; r++)
                vt[r] = fmaf(bprev, vcur[r], fmaf(gprev, cprev[r], R[r]));

            // (3') state update + output (independent of the new chain)
            float4 po = make_float4(0.f, 0.f, 0.f, 0.f);
#pragma unroll
            for (int r = 0; r < R_ROWS; r++) {
                const float cr = cs[r];
                st[r].x = fmaf(st[r].x, gg.x, fmaf(vt[r], bb.x, cr * dd.x));
                st[r].y = fmaf(st[r].y, gg.y, fmaf(vt[r], bb.y, cr * dd.y));
                st[r].z = fmaf(st[r].z, gg.z, fmaf(vt[r], bb.z, cr * dd.z));
                st[r].w = fmaf(st[r].w, gg.w, fmaf(vt[r], bb.w, cr * dd.w));
                const float sr = ss[r];
                po.x = fmaf(sr, st[r].x, po.x);
                po.y = fmaf(sr, st[r].y, po.y);
                po.z = fmaf(sr, st[r].z, po.z);
                po.w = fmaf(sr, st[r].w, po.w);
            }
            float* ob = opart +
                ((size_t)((size_t)t * B_DIM + b) * G_GRP + g) * F_DIM + 4 * l;
            *(float4*)ob = po;

            // rotate pipeline registers
#pragma unroll
            for (int r = 0; r < R_ROWS; r++) {
                R[r] = Rn[r];
                vcur[r] = vt[r];
                cprev[r] = cs[r];
            }
            bprev = beta;
            gprev = gamma;
        }

        __syncwarp();
        if (cc + 3 < NCHUNK) ISSUE_CHUNK(cc + 3);
    }
#undef ISSUE_CHUNK
#undef ALLSUM4

    float* so = state_out + ((size_t)b * F_DIM + rowbase) * F_DIM + 4 * l;
#pragma unroll
    for (int r = 0; r < R_ROWS; r++)
        *(float4*)(so + r * F_DIM) = st[r];
}

// ---------------------------------------------------------------------------
// K3: reduce partials over G -> bf16 hi/lo o
// ---------------------------------------------------------------------------
__global__ void reduce_opart_kernel(const float* __restrict__ opart)
{
    const int F4 = F_DIM / 4;
    size_t idx = (size_t)blockIdx.x * blockDim.x + threadIdx.x;
    size_t total = (size_t)M_DIM * F4;
    if (idx >= total) return;
    size_t row = idx / F4;
    int f4 = (int)(idx % F4);
    const float4* src = (const float4*)opart + row * (size_t)(G_GRP * F4) + f4;
    float4 acc = make_float4(0.f, 0.f, 0.f, 0.f);
#pragma unroll
    for (int gg = 0; gg < G_GRP; gg++) {
        float4 xv = src[(size_t)gg * F4];
        acc.x += xv.x; acc.y += xv.y; acc.z += xv.z; acc.w += xv.w;
    }
    __nv_bfloat16 h0, l0, h1, l1, h2, l2, h3, l3;
    split1(acc.x, h0, l0); split1(acc.y, h1, l1);
    split1(acc.z, h2, l2); split1(acc.w, h3, l3);
    uint2 ph, pl;
    ph.x = (uint32_t)__bfloat16_as_ushort(h0) | ((uint32_t)__bfloat16_as_ushort(h1) << 16);
    ph.y = (uint32_t)__bfloat16_as_ushort(h2) | ((uint32_t)__bfloat16_as_ushort(h3) << 16);
    pl.x = (uint32_t)__bfloat16_as_ushort(l0) | ((uint32_t)__bfloat16_as_ushort(l1) << 16);
    pl.y = (uint32_t)__bfloat16_as_ushort(l2) | ((uint32_t)__bfloat16_as_ushort(l3) << 16);
    ((uint2*)d_oh)[idx] = ph;
    ((uint2*)d_ol)[idx] = pl;
}

// ---------------------------------------------------------------------------
// launch
// ---------------------------------------------------------------------------
extern "C" void kernel_launch(void* const* d_in, const int* in_sizes, int n_in,
                              void* d_out, int out_size)
{
    const float* x     = (const float*)d_in[0];
    const float* state = (const float*)d_in[1];
    const float* A_w = (const float*)d_in[2];
    const float* A_b = (const float*)d_in[3];
    const float* B_w = (const float*)d_in[4];
    const float* B_b = (const float*)d_in[5];
    const float* C_w = (const float*)d_in[6];
    const float* C_b = (const float*)d_in[7];
    const float* D_w = (const float*)d_in[8];
    const float* D_b = (const float*)d_in[9];
    const float* I_w = (const float*)d_in[10];
    const float* I_b = (const float*)d_in[11];
    const float* S_w = (const float*)d_in[12];
    const float* S_b = (const float*)d_in[13];
    const float* O_w = (const float*)d_in[14];

    float* out = (float*)d_out;

    float *b6, *P, *opart, *stfb;
    float2* bgp;
    __nv_bfloat16 *xh, *xl, *W6h, *W6l, *Owh, *Owl, *oh, *ol;
    cudaGetSymbolAddress((void**)&b6, d_b6);
    cudaGetSymbolAddress((void**)&P, d_P);
    cudaGetSymbolAddress((void**)&opart, d_opart);
    cudaGetSymbolAddress((void**)&stfb, d_stfb);
    cudaGetSymbolAddress((void**)&bgp, d_bg);
    cudaGetSymbolAddress((void**)&xh, d_xh);
    cudaGetSymbolAddress((void**)&xl, d_xl);
    cudaGetSymbolAddress((void**)&W6h, d_W6h);
    cudaGetSymbolAddress((void**)&W6l, d_W6l);
    cudaGetSymbolAddress((void**)&Owh, d_Owh);
    cudaGetSymbolAddress((void**)&Owl, d_Owl);
    cudaGetSymbolAddress((void**)&oh, d_oh);
    cudaGetSymbolAddress((void**)&ol, d_ol);

    cudaFuncSetAttribute(bf16_gemm_async,
                         cudaFuncAttributeMaxDynamicSharedMemorySize, GEMM_SMEM);
    cudaFuncSetAttribute(scan_kernel,
                         cudaFuncAttributeMaxDynamicSharedMemorySize, SCAN_SMEM);

    const size_t y_elems = (size_t)M_DIM * C_DIM;
    const size_t st_elems = (size_t)B_DIM * F_DIM * F_DIM;
    float* y = out;
    float* state_out =
        ((size_t)out_size >= y_elems + st_elems) ? (out + y_elems) : stfb;

    // pos 1: pack weights + split x
    {
        size_t total4 = (size_t)M_DIM * C_DIM / 4;
        pack_split_kernel<<<(unsigned)((total4 + 255) / 256), 256>>>(
            x, A_w, B_w, C_w, D_w, I_w, S_w,
            A_b, B_b, C_b, D_b, I_b, S_b, O_w);
    }

    // pos 2: K1  P = x @ W6^T + b6 (+ b-scale / i-sigmoid epilogue)
    {
        dim3 grid(N6 / 128, M_DIM / 128);
        bf16_gemm_async<<<grid, 256, GEMM_SMEM>>>(xh, xl, W6h, W6l, b6, P,
                                                  M_DIM, N6, C_DIM);
    }

    // pos 3: beta/gamma precompute
    bg_kernel<<<(T_DIM * B_DIM) / 8, 256>>>(P, bgp);

    // pos 4: scan (ncu capture position) — lookahead-1 pipelined reduction
    {
        dim3 grid(G_GRP, B_DIM);
        scan_kernel<<<grid, 32, SCAN_SMEM>>>(P, state, bgp, opart, state_out);
    }

    // pos 5: reduce partials -> bf16 hi/lo o
    {
        size_t total = (size_t)M_DIM * (F_DIM / 4);
        reduce_opart_kernel<<<(unsigned)((total + 255) / 256), 256>>>(opart);
    }

    // pos 6: K4  y = o @ O_w^T
    {
        dim3 grid(C_DIM / 128, M_DIM / 128);
        bf16_gemm_async<<<grid, 256, GEMM_SMEM>>>(oh, ol, Owh, Owl, nullptr, y,
                                                  M_DIM, C_DIM, F_DIM);
    }
}